// round 6
// baseline (speedup 1.0000x reference)
#include <cuda_runtime.h>
#include <cuda_bf16.h>

#define OUT_UNITS 128
#define MAX_ROWS  16384
#define WARPS_PER_BLOCK 8

// ---------------------------------------------------------------------------
// Scratch (device globals — no allocation allowed in kernel_launch)
// ---------------------------------------------------------------------------
__device__ int g_is64;                       // 1 if rows/cols are int64, 0 if int32
__device__ int g_row_start[MAX_ROWS + 1];    // CSR-style row offsets

// ---------------------------------------------------------------------------
// Dtype probe: rows sorted ascending over [0, 16384). If int64 (LE), every odd
// 32-bit word is a zero high-half. If int32, odd words near n/4, n/2, 3n/4 are
// sorted row ids ~4096/8192/12288. Probed indices odd and < n: safe for both.
// ---------------------------------------------------------------------------
__device__ __forceinline__ int probe_is64(const int* __restrict__ rows32, int n) {
    int j1 = (n / 2) | 1;
    int j2 = (n / 4) | 1;
    int j3 = (int)(((long long)3 * n) / 4) | 1;
    int s = rows32[j1] | rows32[j2] | rows32[j3];
    return (s == 0) ? 1 : 0;
}

// ---------------------------------------------------------------------------
// Kernel 1: build row offsets from sorted COO rows (fused dtype detection).
// ---------------------------------------------------------------------------
__global__ void build_offsets_kernel(const int* __restrict__ rows32, int nnz, int n_rows) {
    const int is64 = probe_is64(rows32, nnz);

    const int t  = blockIdx.x * blockDim.x + threadIdx.x;
    if (t == 0) g_is64 = is64;
    const int k0 = t * 4;
    if (k0 >= nnz) return;

    const int cnt = min(4, nnz - k0);
    int r[4];
    if (is64) {
        if (cnt == 4) {
            const int4 a = ((const int4*)rows32)[k0 / 2];
            const int4 b = ((const int4*)rows32)[k0 / 2 + 1];
            r[0] = a.x; r[1] = a.z; r[2] = b.x; r[3] = b.z;
        } else {
            for (int j = 0; j < cnt; j++) r[j] = rows32[2 * (k0 + j)];
        }
    } else {
        if (cnt == 4) {
            const int4 a = ((const int4*)rows32)[k0 / 4];
            r[0] = a.x; r[1] = a.y; r[2] = a.z; r[3] = a.w;
        } else {
            for (int j = 0; j < cnt; j++) r[j] = rows32[k0 + j];
        }
    }

    int rp = (k0 == 0) ? -1 : (is64 ? rows32[2 * (k0 - 1)] : rows32[k0 - 1]);
    for (int j = 0; j < cnt; j++) {
        const int rj = r[j];
        for (int x = rp + 1; x <= rj; x++) g_row_start[x] = k0 + j;
        rp = rj;
    }
    if (k0 + cnt == nnz) {
        for (int x = rp + 1; x <= n_rows; x++) g_row_start[x] = nnz;
    }
}

// ---------------------------------------------------------------------------
// Kernel 2: main SpMM. One WARP per output row; lane t owns output columns
// [4t, 4t+4) via float4.
//
// Two-level software pipeline:
//  - Within chunk: ping-pong batches of 4 LDG.128 — while FMAs consume batch
//    A, batch B's gathers are in flight (time-averaged ~8 loads outstanding,
//    only 2 batches of registers live).
//  - Across chunks: next chunk's (val, col) streaming loads issued before the
//    gather loop, published to the alternate smem buffer after.
// Chunks padded with (v=0, c=0): dummy gathers hit the L2-hot row-0 line.
// W gathers use __ldcg (L2-only; random gathers barely hit L1 anyway).
// ---------------------------------------------------------------------------
__global__ void __launch_bounds__(32 * WARPS_PER_BLOCK, 4)
spmm_kernel(const float* __restrict__ values,
            const float* __restrict__ w,
            const int*   __restrict__ cols32,
            float*       __restrict__ out) {
    const int warp = threadIdx.x >> 5;
    const int lane = threadIdx.x & 31;
    const int r    = blockIdx.x * WARPS_PER_BLOCK + warp;
    const int is64 = g_is64;

    __shared__ float sval[2][WARPS_PER_BLOCK][32];
    __shared__ int   scol[2][WARPS_PER_BLOCK][32];

    const int lo = g_row_start[r];
    const int hi = g_row_start[r + 1];

    float4 acc0 = make_float4(0.f, 0.f, 0.f, 0.f);
    float4 acc1 = make_float4(0.f, 0.f, 0.f, 0.f);
    const float4* __restrict__ w4 = (const float4*)w;   // w4[c*32 + lane]

    // Prime chunk 0 into buffer 0
    {
        float v = 0.0f; int c = 0;
        const int k = lo + lane;
        if (k < hi) {
            v = __ldcs(&values[k]);
            c = is64 ? __ldcs(&cols32[2 * k]) : __ldcs(&cols32[k]);
        }
        sval[0][warp][lane] = v;
        scol[0][warp][lane] = c;
    }
    __syncwarp();

    int buf = 0;
    #pragma unroll 1
    for (int base = lo; base < hi; base += 32) {
        // Cross-chunk prefetch into registers (overlaps the gather loop)
        float vn = 0.0f; int cn = 0;
        {
            const int kn = base + 32 + lane;
            if (kn < hi) {
                vn = __ldcs(&values[kn]);
                cn = is64 ? __ldcs(&cols32[2 * kn]) : __ldcs(&cols32[kn]);
            }
        }

        // Within-chunk ping-pong: batch of 4 LDG.128 in flight while the
        // previous batch's FMAs run. unroll 2 => compiler alternates register
        // sets without moves.
        float4 wa0, wa1, wa2, wa3;
        {
            const int c0 = scol[buf][warp][0];
            const int c1 = scol[buf][warp][1];
            const int c2 = scol[buf][warp][2];
            const int c3 = scol[buf][warp][3];
            wa0 = __ldcg(&w4[(size_t)c0 * 32 + lane]);
            wa1 = __ldcg(&w4[(size_t)c1 * 32 + lane]);
            wa2 = __ldcg(&w4[(size_t)c2 * 32 + lane]);
            wa3 = __ldcg(&w4[(size_t)c3 * 32 + lane]);
        }

        #pragma unroll 2
        for (int j = 0; j < 32; j += 4) {
            // Issue next batch's gathers (if any) before consuming current.
            float4 wb0, wb1, wb2, wb3;
            const bool more = (j + 4) < 32;
            if (more) {
                const int c0 = scol[buf][warp][j + 4];
                const int c1 = scol[buf][warp][j + 5];
                const int c2 = scol[buf][warp][j + 6];
                const int c3 = scol[buf][warp][j + 7];
                wb0 = __ldcg(&w4[(size_t)c0 * 32 + lane]);
                wb1 = __ldcg(&w4[(size_t)c1 * 32 + lane]);
                wb2 = __ldcg(&w4[(size_t)c2 * 32 + lane]);
                wb3 = __ldcg(&w4[(size_t)c3 * 32 + lane]);
            }

            const float v0 = sval[buf][warp][j + 0];
            const float v1 = sval[buf][warp][j + 1];
            const float v2 = sval[buf][warp][j + 2];
            const float v3 = sval[buf][warp][j + 3];
            acc0.x = fmaf(v0, wa0.x, acc0.x); acc0.y = fmaf(v0, wa0.y, acc0.y);
            acc0.z = fmaf(v0, wa0.z, acc0.z); acc0.w = fmaf(v0, wa0.w, acc0.w);
            acc1.x = fmaf(v1, wa1.x, acc1.x); acc1.y = fmaf(v1, wa1.y, acc1.y);
            acc1.z = fmaf(v1, wa1.z, acc1.z); acc1.w = fmaf(v1, wa1.w, acc1.w);
            acc0.x = fmaf(v2, wa2.x, acc0.x); acc0.y = fmaf(v2, wa2.y, acc0.y);
            acc0.z = fmaf(v2, wa2.z, acc0.z); acc0.w = fmaf(v2, wa2.w, acc0.w);
            acc1.x = fmaf(v3, wa3.x, acc1.x); acc1.y = fmaf(v3, wa3.y, acc1.y);
            acc1.z = fmaf(v3, wa3.z, acc1.z); acc1.w = fmaf(v3, wa3.w, acc1.w);

            if (more) {
                wa0 = wb0; wa1 = wb1; wa2 = wb2; wa3 = wb3;
            }
        }

        // Publish prefetched chunk to the alternate buffer
        sval[buf ^ 1][warp][lane] = vn;
        scol[buf ^ 1][warp][lane] = cn;
        __syncwarp();
        buf ^= 1;
    }

    acc0.x += acc1.x; acc0.y += acc1.y; acc0.z += acc1.z; acc0.w += acc1.w;
    __stcs(&((float4*)out)[(size_t)r * 32 + lane], acc0);
}

// ---------------------------------------------------------------------------
// Launch
// Inputs (metadata order): values f32[NNZ], w f32[8192*128],
//                          rows int{32,64}[NNZ], cols int{32,64}[NNZ], n_rows
// ---------------------------------------------------------------------------
extern "C" void kernel_launch(void* const* d_in, const int* in_sizes, int n_in,
                              void* d_out, int out_size) {
    const float* values = (const float*)d_in[0];
    const float* w      = (const float*)d_in[1];
    const int*   rows32 = (const int*)d_in[2];
    const int*   cols32 = (const int*)d_in[3];
    float*       out    = (float*)d_out;

    const int nnz    = in_sizes[0];
    const int n_rows = out_size / OUT_UNITS;

    const int bs = 256;
    const int nthreads = (nnz + 3) / 4;
    build_offsets_kernel<<<(nthreads + bs - 1) / bs, bs>>>(rows32, nnz, n_rows);

    spmm_kernel<<<n_rows / WARPS_PER_BLOCK, 32 * WARPS_PER_BLOCK>>>(values, w, cols32, out);
}

// round 7
// speedup vs baseline: 2.3084x; 2.3084x over previous
#include <cuda_runtime.h>
#include <cuda_bf16.h>

#define OUT_UNITS 128
#define WARPS_PER_BLOCK 8

// ---------------------------------------------------------------------------
// Dtype probe: rows sorted ascending over [0, 16384). If int64 (LE), every odd
// 32-bit word is a zero high-half. If int32, odd words near n/4, n/2, 3n/4 are
// sorted row ids ~4096/8192/12288. Probed indices odd and < n: safe for both.
// ---------------------------------------------------------------------------
__device__ __forceinline__ int probe_is64(const int* __restrict__ rows32, int n) {
    int j1 = (n / 2) | 1;
    int j2 = (n / 4) | 1;
    int j3 = (int)(((long long)3 * n) / 4) | 1;
    int s = rows32[j1] | rows32[j2] | rows32[j3];
    return (s == 0) ? 1 : 0;
}

// ---------------------------------------------------------------------------
// Warp-cooperative lower_bound over sorted rows (32-ary search, ~5 rounds for
// 1M entries). Returns first index k with rows[k] >= target.
// ---------------------------------------------------------------------------
__device__ __forceinline__ int warp_lower_bound(const int* __restrict__ rows32,
                                                int nnz, int is64, int target) {
    const int lane = threadIdx.x & 31;
    int lo = 0;
    int len = nnz;
    while (len > 32) {
        const long long q = lo + (((long long)len * lane) >> 5);   // q_0 = lo
        const int v = is64 ? rows32[(size_t)q * 2] : rows32[(size_t)q];
        const unsigned mask = __ballot_sync(0xffffffffu, v < target);
        int new_lo, new_hi;
        if (mask) {
            const int h = 31 - __clz(mask);                        // highest lane with v<target
            new_lo = (int)(lo + (((long long)len * h) >> 5));
            new_hi = (h < 31) ? (int)(lo + (((long long)len * (h + 1)) >> 5))
                              : (lo + len);
        } else {
            new_lo = lo;
            new_hi = (int)(lo + ((long long)len >> 5));            // [lo, q_1)
        }
        lo  = new_lo;
        len = new_hi - new_lo;
    }
    int pred = 0;
    if (lane < len) {
        const int v = is64 ? rows32[(size_t)(lo + lane) * 2] : rows32[lo + lane];
        pred = (v < target) ? 1 : 0;
    }
    const unsigned m = __ballot_sync(0xffffffffu, pred);
    return lo + __popc(m);
}

// ---------------------------------------------------------------------------
// Fused SpMM (single launch). One WARP per output row; lane t owns output
// columns [4t, 4t+4) via float4. Row bounds found via warp-cooperative binary
// search (8 warps search 8 bounds, warp 7 also searches the 9th; shared in
// smem). Gather loop is the proven R2 shape: smem (val,col) staging, batches
// of 4 independent LDG.128 (16 L2 sectors in flight), branch-free via (v=0,
// c=0) padding. Next chunk's streaming loads are prefetched into registers
// before the gather loop and published between two __syncwarp()s.
// ---------------------------------------------------------------------------
__global__ void __launch_bounds__(32 * WARPS_PER_BLOCK)
spmm_kernel(const float* __restrict__ values,
            const float* __restrict__ w,
            const int*   __restrict__ rows32,
            const int*   __restrict__ cols32,
            float*       __restrict__ out,
            int nnz) {
    const int warp = threadIdx.x >> 5;
    const int lane = threadIdx.x & 31;
    const int r0   = blockIdx.x * WARPS_PER_BLOCK;

    const int is64 = probe_is64(rows32, nnz);

    __shared__ int    sbounds[WARPS_PER_BLOCK + 1];
    __shared__ float2 stage[WARPS_PER_BLOCK][32];

    // Row-segment bounds: warp w finds lower_bound(r0 + w); warp 7 also finds
    // the closing bound lower_bound(r0 + 8).
    {
        const int b = warp_lower_bound(rows32, nnz, is64, r0 + warp);
        if (lane == 0) sbounds[warp] = b;
        if (warp == WARPS_PER_BLOCK - 1) {
            const int b2 = warp_lower_bound(rows32, nnz, is64, r0 + WARPS_PER_BLOCK);
            if (lane == 0) sbounds[WARPS_PER_BLOCK] = b2;
        }
    }
    __syncthreads();

    const int lo = sbounds[warp];
    const int hi = sbounds[warp + 1];
    const int r  = r0 + warp;

    float4 acc = make_float4(0.f, 0.f, 0.f, 0.f);
    const float4* __restrict__ w4 = (const float4*)w;   // w4[c*32 + lane]

    // Prime chunk 0
    {
        float v = 0.0f; int c = 0;
        const int k = lo + lane;
        if (k < hi) {
            v = values[k];
            c = is64 ? cols32[2 * k] : cols32[k];
        }
        stage[warp][lane] = make_float2(v, __int_as_float(c));
    }
    __syncwarp();

    #pragma unroll 1
    for (int base = lo; base < hi; base += 32) {
        // Cross-chunk prefetch into registers (overlaps the gather loop below)
        float vn = 0.0f; int cn = 0;
        {
            const int kn = base + 32 + lane;
            if (kn < hi) {
                vn = values[kn];
                cn = is64 ? cols32[2 * kn] : cols32[kn];
            }
        }

        const int m = min(32, hi - base);

        // Gather + accumulate: batches of 4 independent LDG.128 (R2 shape)
        int i = 0;
        #pragma unroll 1
        for (; i + 4 <= m; i += 4) {
            const float2 p0 = stage[warp][i + 0];
            const float2 p1 = stage[warp][i + 1];
            const float2 p2 = stage[warp][i + 2];
            const float2 p3 = stage[warp][i + 3];
            const float4 w0 = w4[(size_t)__float_as_int(p0.y) * 32 + lane];
            const float4 w1 = w4[(size_t)__float_as_int(p1.y) * 32 + lane];
            const float4 w2 = w4[(size_t)__float_as_int(p2.y) * 32 + lane];
            const float4 w3 = w4[(size_t)__float_as_int(p3.y) * 32 + lane];
            acc.x = fmaf(p0.x, w0.x, acc.x); acc.y = fmaf(p0.x, w0.y, acc.y);
            acc.z = fmaf(p0.x, w0.z, acc.z); acc.w = fmaf(p0.x, w0.w, acc.w);
            acc.x = fmaf(p1.x, w1.x, acc.x); acc.y = fmaf(p1.x, w1.y, acc.y);
            acc.z = fmaf(p1.x, w1.z, acc.z); acc.w = fmaf(p1.x, w1.w, acc.w);
            acc.x = fmaf(p2.x, w2.x, acc.x); acc.y = fmaf(p2.x, w2.y, acc.y);
            acc.z = fmaf(p2.x, w2.z, acc.z); acc.w = fmaf(p2.x, w2.w, acc.w);
            acc.x = fmaf(p3.x, w3.x, acc.x); acc.y = fmaf(p3.x, w3.y, acc.y);
            acc.z = fmaf(p3.x, w3.z, acc.z); acc.w = fmaf(p3.x, w3.w, acc.w);
        }
        for (; i < m; i++) {
            const float2 p = stage[warp][i];
            const float4 wv = w4[(size_t)__float_as_int(p.y) * 32 + lane];
            acc.x = fmaf(p.x, wv.x, acc.x); acc.y = fmaf(p.x, wv.y, acc.y);
            acc.z = fmaf(p.x, wv.z, acc.z); acc.w = fmaf(p.x, wv.w, acc.w);
        }

        // Publish prefetched chunk (same buffer, fenced by two syncwarps)
        __syncwarp();
        stage[warp][lane] = make_float2(vn, __int_as_float(cn));
        __syncwarp();
    }

    ((float4*)out)[(size_t)r * 32 + lane] = acc;
}

// ---------------------------------------------------------------------------
// Launch — single kernel.
// Inputs (metadata order): values f32[NNZ], w f32[8192*128],
//                          rows int{32,64}[NNZ], cols int{32,64}[NNZ], n_rows
// ---------------------------------------------------------------------------
extern "C" void kernel_launch(void* const* d_in, const int* in_sizes, int n_in,
                              void* d_out, int out_size) {
    const float* values = (const float*)d_in[0];
    const float* w      = (const float*)d_in[1];
    const int*   rows32 = (const int*)d_in[2];
    const int*   cols32 = (const int*)d_in[3];
    float*       out    = (float*)d_out;

    const int nnz    = in_sizes[0];
    const int n_rows = out_size / OUT_UNITS;

    spmm_kernel<<<n_rows / WARPS_PER_BLOCK, 32 * WARPS_PER_BLOCK>>>(
        values, w, rows32, cols32, out, nnz);
}

// round 8
// speedup vs baseline: 2.5902x; 1.1221x over previous
#include <cuda_runtime.h>
#include <cuda_bf16.h>

#define OUT_UNITS 128
#define MAX_ROWS  16384
#define WARPS_PER_BLOCK 8

// ---------------------------------------------------------------------------
// Scratch (device globals — no allocation allowed in kernel_launch)
// ---------------------------------------------------------------------------
__device__ int g_is64;                       // 1 if rows/cols are int64, 0 if int32
__device__ int g_row_start[MAX_ROWS + 1];    // CSR-style row offsets

// ---------------------------------------------------------------------------
// Dtype probe: rows sorted ascending over [0, 16384). If int64 (LE), every odd
// 32-bit word is a zero high-half. If int32, odd words near n/4, n/2, 3n/4 are
// sorted row ids ~4096/8192/12288. Probed indices odd and < n: safe for both.
// ---------------------------------------------------------------------------
__device__ __forceinline__ int probe_is64(const int* __restrict__ rows32, int n) {
    int j1 = (n / 2) | 1;
    int j2 = (n / 4) | 1;
    int j3 = (int)(((long long)3 * n) / 4) | 1;
    int s = rows32[j1] | rows32[j2] | rows32[j3];
    return (s == 0) ? 1 : 0;
}

// ---------------------------------------------------------------------------
// Kernel 1: build row offsets from sorted COO rows (fused dtype detection).
// 4 elements per thread, vectorized int4 loads.
// ---------------------------------------------------------------------------
__global__ void build_offsets_kernel(const int* __restrict__ rows32, int nnz, int n_rows) {
    const int is64 = probe_is64(rows32, nnz);

    const int t  = blockIdx.x * blockDim.x + threadIdx.x;
    if (t == 0) g_is64 = is64;
    const int k0 = t * 4;
    if (k0 >= nnz) return;

    const int cnt = min(4, nnz - k0);
    int r[4];
    if (is64) {
        if (cnt == 4) {
            const int4 a = ((const int4*)rows32)[k0 / 2];
            const int4 b = ((const int4*)rows32)[k0 / 2 + 1];
            r[0] = a.x; r[1] = a.z; r[2] = b.x; r[3] = b.z;
        } else {
            for (int j = 0; j < cnt; j++) r[j] = rows32[2 * (k0 + j)];
        }
    } else {
        if (cnt == 4) {
            const int4 a = ((const int4*)rows32)[k0 / 4];
            r[0] = a.x; r[1] = a.y; r[2] = a.z; r[3] = a.w;
        } else {
            for (int j = 0; j < cnt; j++) r[j] = rows32[k0 + j];
        }
    }

    int rp = (k0 == 0) ? -1 : (is64 ? rows32[2 * (k0 - 1)] : rows32[k0 - 1]);
    for (int j = 0; j < cnt; j++) {
        const int rj = r[j];
        for (int x = rp + 1; x <= rj; x++) g_row_start[x] = k0 + j;
        rp = rj;
    }
    if (k0 + cnt == nnz) {
        for (int x = rp + 1; x <= n_rows; x++) g_row_start[x] = nnz;
    }
}

// ---------------------------------------------------------------------------
// Kernel 2: main SpMM — R2 skeleton + double-buffered cross-chunk prefetch.
// One WARP per output row; lane t owns output columns [4t, 4t+4) via float4.
// Per 32-nnz chunk: next chunk's (val, col) streaming loads are issued into
// registers BEFORE the gather loop (their DRAM latency hides under ~2000 cyc
// of W gathers), then published to the alternate smem buffer after it.
// Gather loop: branch-free batches of 4 independent LDG.128 (16 L2 sectors in
// flight per warp); chunks padded to a multiple of 4 with (v=0, c=0) dummies
// (dummy gathers hit the L2/L1-hot row-0 line).
// ---------------------------------------------------------------------------
__global__ void __launch_bounds__(32 * WARPS_PER_BLOCK)
spmm_kernel(const float* __restrict__ values,
            const float* __restrict__ w,
            const int*   __restrict__ cols32,
            float*       __restrict__ out) {
    const int warp = threadIdx.x >> 5;
    const int lane = threadIdx.x & 31;
    const int r    = blockIdx.x * WARPS_PER_BLOCK + warp;
    const int is64 = g_is64;

    __shared__ float2 stage[2][WARPS_PER_BLOCK][32];

    const int lo = g_row_start[r];
    const int hi = g_row_start[r + 1];

    float4 acc = make_float4(0.f, 0.f, 0.f, 0.f);
    const float4* __restrict__ w4 = (const float4*)w;   // w4[c*32 + lane]

    // Prime chunk 0 into buffer 0 (pad with v=0, c=0)
    {
        float v = 0.0f; int c = 0;
        const int k = lo + lane;
        if (k < hi) {
            v = values[k];
            c = is64 ? cols32[2 * k] : cols32[k];
        }
        stage[0][warp][lane] = make_float2(v, __int_as_float(c));
    }
    __syncwarp();

    int buf = 0;
    #pragma unroll 1
    for (int base = lo; base < hi; base += 32) {
        // Cross-chunk prefetch into registers (overlaps the gather loop below)
        float vn = 0.0f; int cn = 0;
        {
            const int kn = base + 32 + lane;
            if (kn < hi) {
                vn = values[kn];
                cn = is64 ? cols32[2 * kn] : cols32[kn];
            }
        }

        const int m  = min(32, hi - base);
        const int mm = (m + 3) & ~3;                    // padded to multiple of 4

        // Gather + accumulate: branch-free batches of 4 independent LDG.128
        #pragma unroll 1
        for (int i = 0; i < mm; i += 4) {
            const float2 p0 = stage[buf][warp][i + 0];
            const float2 p1 = stage[buf][warp][i + 1];
            const float2 p2 = stage[buf][warp][i + 2];
            const float2 p3 = stage[buf][warp][i + 3];
            const float4 w0 = w4[(size_t)__float_as_int(p0.y) * 32 + lane];
            const float4 w1 = w4[(size_t)__float_as_int(p1.y) * 32 + lane];
            const float4 w2 = w4[(size_t)__float_as_int(p2.y) * 32 + lane];
            const float4 w3 = w4[(size_t)__float_as_int(p3.y) * 32 + lane];
            acc.x = fmaf(p0.x, w0.x, acc.x); acc.y = fmaf(p0.x, w0.y, acc.y);
            acc.z = fmaf(p0.x, w0.z, acc.z); acc.w = fmaf(p0.x, w0.w, acc.w);
            acc.x = fmaf(p1.x, w1.x, acc.x); acc.y = fmaf(p1.x, w1.y, acc.y);
            acc.z = fmaf(p1.x, w1.z, acc.z); acc.w = fmaf(p1.x, w1.w, acc.w);
            acc.x = fmaf(p2.x, w2.x, acc.x); acc.y = fmaf(p2.x, w2.y, acc.y);
            acc.z = fmaf(p2.x, w2.z, acc.z); acc.w = fmaf(p2.x, w2.w, acc.w);
            acc.x = fmaf(p3.x, w3.x, acc.x); acc.y = fmaf(p3.x, w3.y, acc.y);
            acc.z = fmaf(p3.x, w3.z, acc.z); acc.w = fmaf(p3.x, w3.w, acc.w);
        }

        // Publish prefetched chunk to the alternate buffer
        stage[buf ^ 1][warp][lane] = make_float2(vn, __int_as_float(cn));
        __syncwarp();
        buf ^= 1;
    }

    ((float4*)out)[(size_t)r * 32 + lane] = acc;
}

// ---------------------------------------------------------------------------
// Launch
// Inputs (metadata order): values f32[NNZ], w f32[8192*128],
//                          rows int{32,64}[NNZ], cols int{32,64}[NNZ], n_rows
// ---------------------------------------------------------------------------
extern "C" void kernel_launch(void* const* d_in, const int* in_sizes, int n_in,
                              void* d_out, int out_size) {
    const float* values = (const float*)d_in[0];
    const float* w      = (const float*)d_in[1];
    const int*   rows32 = (const int*)d_in[2];
    const int*   cols32 = (const int*)d_in[3];
    float*       out    = (float*)d_out;

    const int nnz    = in_sizes[0];
    const int n_rows = out_size / OUT_UNITS;

    const int bs = 256;
    const int nthreads = (nnz + 3) / 4;
    build_offsets_kernel<<<(nthreads + bs - 1) / bs, bs>>>(rows32, nnz, n_rows);

    spmm_kernel<<<n_rows / WARPS_PER_BLOCK, 32 * WARPS_PER_BLOCK>>>(values, w, cols32, out);
}

// round 9
// speedup vs baseline: 2.9901x; 1.1544x over previous
#include <cuda_runtime.h>
#include <cuda_bf16.h>

#define OUT_UNITS 128
#define MAX_ROWS  16384
#define WARPS_PER_BLOCK 4

// ---------------------------------------------------------------------------
// Scratch (device globals — no allocation allowed in kernel_launch)
// ---------------------------------------------------------------------------
__device__ int g_is64;                       // 1 if rows/cols are int64, 0 if int32
__device__ int g_row_start[MAX_ROWS + 1];    // CSR-style row offsets

// ---------------------------------------------------------------------------
// Dtype probe: rows sorted ascending over [0, 16384). If int64 (LE), every odd
// 32-bit word is a zero high-half. If int32, odd words near n/4, n/2, 3n/4 are
// sorted row ids ~4096/8192/12288. Probed indices odd and < n: safe for both.
// ---------------------------------------------------------------------------
__device__ __forceinline__ int probe_is64(const int* __restrict__ rows32, int n) {
    int j1 = (n / 2) | 1;
    int j2 = (n / 4) | 1;
    int j3 = (int)(((long long)3 * n) / 4) | 1;
    int s = rows32[j1] | rows32[j2] | rows32[j3];
    return (s == 0) ? 1 : 0;
}

// ---------------------------------------------------------------------------
// Kernel 1: build row offsets from sorted COO rows (fused dtype detection).
// 4 elements per thread, vectorized int4 loads.
// ---------------------------------------------------------------------------
__global__ void build_offsets_kernel(const int* __restrict__ rows32, int nnz, int n_rows) {
    const int is64 = probe_is64(rows32, nnz);

    const int t  = blockIdx.x * blockDim.x + threadIdx.x;
    if (t == 0) g_is64 = is64;
    const int k0 = t * 4;
    if (k0 >= nnz) return;

    const int cnt = min(4, nnz - k0);
    int r[4];
    if (is64) {
        if (cnt == 4) {
            const int4 a = ((const int4*)rows32)[k0 / 2];
            const int4 b = ((const int4*)rows32)[k0 / 2 + 1];
            r[0] = a.x; r[1] = a.z; r[2] = b.x; r[3] = b.z;
        } else {
            for (int j = 0; j < cnt; j++) r[j] = rows32[2 * (k0 + j)];
        }
    } else {
        if (cnt == 4) {
            const int4 a = ((const int4*)rows32)[k0 / 4];
            r[0] = a.x; r[1] = a.y; r[2] = a.z; r[3] = a.w;
        } else {
            for (int j = 0; j < cnt; j++) r[j] = rows32[k0 + j];
        }
    }

    int rp = (k0 == 0) ? -1 : (is64 ? rows32[2 * (k0 - 1)] : rows32[k0 - 1]);
    for (int j = 0; j < cnt; j++) {
        const int rj = r[j];
        for (int x = rp + 1; x <= rj; x++) g_row_start[x] = k0 + j;
        rp = rj;
    }
    if (k0 + cnt == nnz) {
        for (int x = rp + 1; x <= n_rows; x++) g_row_start[x] = nnz;
    }
}

// ---------------------------------------------------------------------------
// Kernel 2: main SpMM — exact R2 inner loop (best measured: 34.3 us), in
// 4-warp CTAs to reduce intra-CTA max-of-warps residency tail.
// One WARP per output row; lane t owns output columns [4t, 4t+4) via float4.
// Stage 32 (val, col) pairs per warp in smem (broadcast LDS reads), gather W
// rows with batches of 4 independent LDG.128 (16 L2 sectors in flight).
// ---------------------------------------------------------------------------
__global__ void __launch_bounds__(32 * WARPS_PER_BLOCK)
spmm_kernel(const float* __restrict__ values,
            const float* __restrict__ w,
            const int*   __restrict__ cols32,
            float*       __restrict__ out) {
    const int warp = threadIdx.x >> 5;
    const int lane = threadIdx.x & 31;
    const int r    = blockIdx.x * WARPS_PER_BLOCK + warp;
    const int is64 = g_is64;

    __shared__ float2 stage[WARPS_PER_BLOCK][32];

    const int lo = g_row_start[r];
    const int hi = g_row_start[r + 1];

    float4 acc = make_float4(0.f, 0.f, 0.f, 0.f);
    const float4* __restrict__ w4 = (const float4*)w;   // w4[c*32 + lane]

    for (int base = lo; base < hi; base += 32) {
        const int m = min(32, hi - base);
        if (lane < m) {
            const int k = base + lane;
            const int c = is64 ? cols32[2 * k] : cols32[k];
            stage[warp][lane] = make_float2(values[k], __int_as_float(c));
        }
        __syncwarp();

        int i = 0;
        #pragma unroll 1
        for (; i + 4 <= m; i += 4) {
            const float2 p0 = stage[warp][i + 0];
            const float2 p1 = stage[warp][i + 1];
            const float2 p2 = stage[warp][i + 2];
            const float2 p3 = stage[warp][i + 3];
            // 4 independent coalesced LDG.128s in flight
            const float4 w0 = w4[(size_t)__float_as_int(p0.y) * 32 + lane];
            const float4 w1 = w4[(size_t)__float_as_int(p1.y) * 32 + lane];
            const float4 w2 = w4[(size_t)__float_as_int(p2.y) * 32 + lane];
            const float4 w3 = w4[(size_t)__float_as_int(p3.y) * 32 + lane];
            acc.x = fmaf(p0.x, w0.x, acc.x); acc.y = fmaf(p0.x, w0.y, acc.y);
            acc.z = fmaf(p0.x, w0.z, acc.z); acc.w = fmaf(p0.x, w0.w, acc.w);
            acc.x = fmaf(p1.x, w1.x, acc.x); acc.y = fmaf(p1.x, w1.y, acc.y);
            acc.z = fmaf(p1.x, w1.z, acc.z); acc.w = fmaf(p1.x, w1.w, acc.w);
            acc.x = fmaf(p2.x, w2.x, acc.x); acc.y = fmaf(p2.x, w2.y, acc.y);
            acc.z = fmaf(p2.x, w2.z, acc.z); acc.w = fmaf(p2.x, w2.w, acc.w);
            acc.x = fmaf(p3.x, w3.x, acc.x); acc.y = fmaf(p3.x, w3.y, acc.y);
            acc.z = fmaf(p3.x, w3.z, acc.z); acc.w = fmaf(p3.x, w3.w, acc.w);
        }
        for (; i < m; i++) {
            const float2 p = stage[warp][i];
            const float4 wv = w4[(size_t)__float_as_int(p.y) * 32 + lane];
            acc.x = fmaf(p.x, wv.x, acc.x); acc.y = fmaf(p.x, wv.y, acc.y);
            acc.z = fmaf(p.x, wv.z, acc.z); acc.w = fmaf(p.x, wv.w, acc.w);
        }
        __syncwarp();
    }

    ((float4*)out)[(size_t)r * 32 + lane] = acc;
}

// ---------------------------------------------------------------------------
// Launch
// Inputs (metadata order): values f32[NNZ], w f32[8192*128],
//                          rows int{32,64}[NNZ], cols int{32,64}[NNZ], n_rows
// ---------------------------------------------------------------------------
extern "C" void kernel_launch(void* const* d_in, const int* in_sizes, int n_in,
                              void* d_out, int out_size) {
    const float* values = (const float*)d_in[0];
    const float* w      = (const float*)d_in[1];
    const int*   rows32 = (const int*)d_in[2];
    const int*   cols32 = (const int*)d_in[3];
    float*       out    = (float*)d_out;

    const int nnz    = in_sizes[0];
    const int n_rows = out_size / OUT_UNITS;

    const int bs = 256;
    const int nthreads = (nnz + 3) / 4;
    build_offsets_kernel<<<(nthreads + bs - 1) / bs, bs>>>(rows32, nnz, n_rows);

    spmm_kernel<<<n_rows / WARPS_PER_BLOCK, 32 * WARPS_PER_BLOCK>>>(values, w, cols32, out);
}